// round 15
// baseline (speedup 1.0000x reference)
#include <cuda_runtime.h>
#include <cuda_bf16.h>
#include <math.h>
#include <stdint.h>

// Model dims
#define BT   2
#define TT   2048
#define NTOK 4096
#define DM   512
#define NH   8
#define HSZ  64
#define FFD  2048
#define NL   6
#define VOC  32000

// Scratch
__device__ float g_x [NTOK * DM];
__device__ float g_h [NTOK * DM];
__device__ float g_q [NTOK * DM];
__device__ float g_k [NTOK * DM];
__device__ float g_v [NTOK * DM];
__device__ float g_a [NTOK * DM];
__device__ float g_ff[NTOK * FFD];
__device__ float g_red[2];
__device__ float g_part[2 * NTOK * DM];
__device__ float g_sm[2 * NTOK * NH];
__device__ float g_sl[2 * NTOK * NH];
__device__ float g_logits_fb[(size_t)NTOK * VOC];

// ---------------------------------------------------------------------------
__device__ __forceinline__ float warpSum(float v) {
#pragma unroll
    for (int o = 16; o > 0; o >>= 1) v += __shfl_xor_sync(0xffffffffu, v, o);
    return v;
}
__device__ __forceinline__ float warpMax(float v) {
#pragma unroll
    for (int o = 16; o > 0; o >>= 1) v = fmaxf(v, __shfl_xor_sync(0xffffffffu, v, o));
    return v;
}

// ---------------------------------------------------------------------------
__global__ void embed_kernel(const int* __restrict__ toks,
                             const float* __restrict__ temb,
                             const float* __restrict__ pemb,
                             float* __restrict__ x) {
    int i = blockIdx.x * blockDim.x + threadIdx.x;
    if (i >= NTOK * DM / 4) return;
    int n  = i / (DM / 4);
    int c  = i % (DM / 4);
    int tk = toks[n];
    int t  = n % TT;
    float4 a = ((const float4*)temb)[(size_t)tk * (DM / 4) + c];
    float4 p = ((const float4*)pemb)[(size_t)t  * (DM / 4) + c];
    float4 r;
    r.x = a.x + p.x; r.y = a.y + p.y; r.z = a.z + p.z; r.w = a.w + p.w;
    ((float4*)x)[i] = r;
}

// ---------------------------------------------------------------------------
__global__ void ln_kernel(const float* __restrict__ in, float* __restrict__ out,
                          const float* __restrict__ gamma, const float* __restrict__ beta) {
    int row = blockIdx.x;
    int tid = threadIdx.x;
    const float4 v4 = ((const float4*)(in + (size_t)row * DM))[tid];
    float s  = v4.x + v4.y + v4.z + v4.w;
    float s2 = v4.x * v4.x + v4.y * v4.y + v4.z * v4.z + v4.w * v4.w;

    __shared__ float rs[4], rs2[4];
    int warp = tid >> 5, lane = tid & 31;
    s = warpSum(s); s2 = warpSum(s2);
    if (lane == 0) { rs[warp] = s; rs2[warp] = s2; }
    __syncthreads();
    float ts = 0.f, ts2 = 0.f;
#pragma unroll
    for (int w = 0; w < 4; w++) { ts += rs[w]; ts2 += rs2[w]; }
    float mean = ts * (1.0f / DM);
    float var  = ts2 * (1.0f / DM) - mean * mean;
    float rstd = rsqrtf(var + 1e-5f);

    float4 g4 = ((const float4*)gamma)[tid];
    float4 b4 = ((const float4*)beta)[tid];
    float4 o;
    o.x = (v4.x - mean) * rstd * g4.x + b4.x;
    o.y = (v4.y - mean) * rstd * g4.y + b4.y;
    o.z = (v4.z - mean) * rstd * g4.z + b4.z;
    o.w = (v4.w - mean) * rstd * g4.w + b4.w;
    ((float4*)(out + (size_t)row * DM))[tid] = o;
}

// ---------------------------------------------------------------------------
// bf16x3 helpers
// ---------------------------------------------------------------------------
__device__ __forceinline__ void cpa16(uint32_t s, const void* g) {
    asm volatile("cp.async.cg.shared.global [%0], [%1], 16;\n" :: "r"(s), "l"(g));
}

__device__ __forceinline__ uint32_t bfb(float x) {
    return (uint32_t)__bfloat16_as_ushort(__float2bfloat16(x));
}
__device__ __forceinline__ void split2pack(float e, float o, uint32_t& hp, uint32_t& lp) {
    uint32_t he = bfb(e), ho = bfb(o);
    float re = e - __uint_as_float(he << 16);
    float ro = o - __uint_as_float(ho << 16);
    hp = he | (ho << 16);
    lp = bfb(re) | (bfb(ro) << 16);
}

__device__ __forceinline__ void mma_bf(float (&c)[4], const unsigned (&A)[4], const unsigned (&B)[2]) {
    asm volatile(
        "mma.sync.aligned.m16n8k16.row.col.f32.bf16.bf16.f32 "
        "{%0,%1,%2,%3}, {%4,%5,%6,%7}, {%8,%9}, {%0,%1,%2,%3};\n"
        : "+f"(c[0]), "+f"(c[1]), "+f"(c[2]), "+f"(c[3])
        : "r"(A[0]), "r"(A[1]), "r"(A[2]), "r"(A[3]), "r"(B[0]), "r"(B[1]));
}

// ---------------------------------------------------------------------------
// bf16x3 tensor-core GEMM, BN=64 (QKV / Wo / FF2)
// ---------------------------------------------------------------------------
#define ASTR 36
#define BSTR 72
#define APSTR 20
#define BPSTR 72

template<int MT, int BIAS, int RES, int RELU, int QKV>
__global__ void __launch_bounds__(256)
tgemm(const float* __restrict__ A,
      const float* __restrict__ B0, const float* __restrict__ B1, const float* __restrict__ B2,
      const float* __restrict__ bias, const float* __restrict__ res,
      float* __restrict__ C0, float* __restrict__ C1, float* __restrict__ C2,
      int K, int lda, int ldb, int ldc, long bz, long cz) {
    constexpr int BM   = MT * 64;
    constexpr int ABUF = BM * ASTR;
    constexpr int BBUF = 32 * BSTR;

    extern __shared__ float smm[];
    float* sA = smm;
    float* sB = smm + 2 * ABUF;
    uint32_t* sAh = (uint32_t*)(sB + 2 * BBUF);
    uint32_t* sAl = sAh + BM * APSTR;
    uint32_t* sBh = sAl + BM * APSTR;
    uint32_t* sBl = sBh + 16 * BPSTR;

    const float* B;
    float* C;
    if (QKV) {
        int z = blockIdx.z, sel = z >> 3, head = z & 7;
        const float* Bp = (sel == 0) ? B0 : (sel == 1) ? B1 : B2;
        float*       Cp = (sel == 0) ? C0 : (sel == 1) ? C1 : C2;
        B = Bp + (long)head * bz;
        C = Cp + (long)head * cz;
    } else {
        B = B0 + (long)blockIdx.z * bz;
        C = C0 + (long)blockIdx.z * cz;
    }

    int tid = threadIdx.x;
    int rowBase = blockIdx.y * BM;
    int colBase = blockIdx.x * 64;

    uint32_t sAaddr = (uint32_t)__cvta_generic_to_shared(sA);
    uint32_t sBaddr = (uint32_t)__cvta_generic_to_shared(sB);

    int ntiles = K >> 5;

    {
#pragma unroll
        for (int i = 0; i < 2 * MT; i++) {
            int idx = tid + i * 256;
            int r = idx >> 3, c = (idx & 7) * 4;
            cpa16(sAaddr + (uint32_t)(r * ASTR + c) * 4,
                  A + (size_t)(rowBase + r) * lda + c);
        }
#pragma unroll
        for (int i = 0; i < 2; i++) {
            int idx = tid + i * 256;
            int r = idx >> 4, c = (idx & 15) * 4;
            cpa16(sBaddr + (uint32_t)(r * BSTR + c) * 4,
                  B + (size_t)r * ldb + colBase + c);
        }
        asm volatile("cp.async.commit_group;\n");
    }

    float acc[MT][4][4] = {};
    int lane = tid & 31, warp = tid >> 5;
    int wm = warp >> 1, wn = warp & 1;
    int g = lane >> 2, tg = lane & 3;

    for (int t = 0; t < ntiles; t++) {
        asm volatile("cp.async.wait_group 0;\n");
        __syncthreads();
        int cur = t & 1, nxt = cur ^ 1;

        if (t + 1 < ntiles) {
            int k0 = (t + 1) << 5;
#pragma unroll
            for (int i = 0; i < 2 * MT; i++) {
                int idx = tid + i * 256;
                int r = idx >> 3, c = (idx & 7) * 4;
                cpa16(sAaddr + (uint32_t)(nxt * ABUF + r * ASTR + c) * 4,
                      A + (size_t)(rowBase + r) * lda + k0 + c);
            }
#pragma unroll
            for (int i = 0; i < 2; i++) {
                int idx = tid + i * 256;
                int r = idx >> 4, c = (idx & 15) * 4;
                cpa16(sBaddr + (uint32_t)(nxt * BBUF + r * BSTR + c) * 4,
                      B + (size_t)(k0 + r) * ldb + colBase + c);
            }
            asm volatile("cp.async.commit_group;\n");
        }

        {
            const float* cA = sA + cur * ABUF;
#pragma unroll
            for (int i = 0; i < 2 * MT; i++) {
                int idx = tid + i * 256;
                int r = idx >> 3, cg = idx & 7;
                float4 xa = *(const float4*)(cA + r * ASTR + 4 * cg);
                uint32_t h0, l0, h1, l1;
                split2pack(xa.x, xa.y, h0, l0);
                split2pack(xa.z, xa.w, h1, l1);
                *(uint2*)&sAh[r * APSTR + 2 * cg] = make_uint2(h0, h1);
                *(uint2*)&sAl[r * APSTR + 2 * cg] = make_uint2(l0, l1);
            }
            const float* cBs = sB + cur * BBUF;
            int kp = tid >> 4, cg = tid & 15, c = 4 * cg;
            float4 b0 = *(const float4*)(cBs + (2 * kp)     * BSTR + c);
            float4 b1 = *(const float4*)(cBs + (2 * kp + 1) * BSTR + c);
            uint32_t h[4], l[4];
            split2pack(b0.x, b1.x, h[0], l[0]);
            split2pack(b0.y, b1.y, h[1], l[1]);
            split2pack(b0.z, b1.z, h[2], l[2]);
            split2pack(b0.w, b1.w, h[3], l[3]);
            *(uint4*)&sBh[kp * BPSTR + c] = make_uint4(h[0], h[1], h[2], h[3]);
            *(uint4*)&sBl[kp * BPSTR + c] = make_uint4(l[0], l[1], l[2], l[3]);
        }
        __syncthreads();

#pragma unroll
        for (int kk = 0; kk < 2; kk++) {
            unsigned ah[MT][4], al[MT][4];
#pragma unroll
            for (int mt = 0; mt < MT; mt++) {
                int mb = wm * (MT * 16) + mt * 16;
                ah[mt][0] = sAh[(mb + g)     * APSTR + 8 * kk + tg];
                ah[mt][1] = sAh[(mb + 8 + g) * APSTR + 8 * kk + tg];
                ah[mt][2] = sAh[(mb + g)     * APSTR + 8 * kk + tg + 4];
                ah[mt][3] = sAh[(mb + 8 + g) * APSTR + 8 * kk + tg + 4];
                al[mt][0] = sAl[(mb + g)     * APSTR + 8 * kk + tg];
                al[mt][1] = sAl[(mb + 8 + g) * APSTR + 8 * kk + tg];
                al[mt][2] = sAl[(mb + g)     * APSTR + 8 * kk + tg + 4];
                al[mt][3] = sAl[(mb + 8 + g) * APSTR + 8 * kk + tg + 4];
            }
#pragma unroll
            for (int nt = 0; nt < 4; nt++) {
                int nb = wn * 32 + nt * 8;
                unsigned bh[2], bl[2];
                bh[0] = sBh[(8 * kk + tg)     * BPSTR + nb + g];
                bh[1] = sBh[(8 * kk + tg + 4) * BPSTR + nb + g];
                bl[0] = sBl[(8 * kk + tg)     * BPSTR + nb + g];
                bl[1] = sBl[(8 * kk + tg + 4) * BPSTR + nb + g];
#pragma unroll
                for (int mt = 0; mt < MT; mt++) {
                    mma_bf(acc[mt][nt], al[mt], bh);
                    mma_bf(acc[mt][nt], ah[mt], bl);
                    mma_bf(acc[mt][nt], ah[mt], bh);
                }
            }
        }
        __syncthreads();
    }

#pragma unroll
    for (int mt = 0; mt < MT; mt++) {
#pragma unroll
        for (int nt = 0; nt < 4; nt++) {
            int r0 = rowBase + wm * (MT * 16) + mt * 16 + g;
            int c0 = colBase + wn * 32 + nt * 8 + 2 * tg;
            float bx = 0.f, by = 0.f;
            if (BIAS) { bx = bias[c0]; by = bias[c0 + 1]; }
            size_t o0 = (size_t)r0 * ldc + c0;
            size_t o1 = (size_t)(r0 + 8) * ldc + c0;
            float v0 = acc[mt][nt][0] + bx;
            float v1 = acc[mt][nt][1] + by;
            float v2 = acc[mt][nt][2] + bx;
            float v3 = acc[mt][nt][3] + by;
            if (RES) {
                v0 += res[o0]; v1 += res[o0 + 1];
                v2 += res[o1]; v3 += res[o1 + 1];
            }
            if (RELU) {
                v0 = fmaxf(v0, 0.f); v1 = fmaxf(v1, 0.f);
                v2 = fmaxf(v2, 0.f); v3 = fmaxf(v3, 0.f);
            }
            C[o0] = v0; C[o0 + 1] = v1;
            C[o1] = v2; C[o1 + 1] = v3;
        }
    }
}

#define SMEM_MT1 ((2 * (64  * ASTR) + 2 * (32 * BSTR) + 2 * (64  * APSTR) + 2 * (16 * BPSTR)) * 4)

// ---------------------------------------------------------------------------
// bf16x3 GEMM, BM=128 x BN=128 (FF1, logits): halves operand re-streaming.
// 8 warps as 2m x 4n; warp tile 64x32; acc[4][4][4].
// ---------------------------------------------------------------------------
#define B2STR  132
#define BP2STR 132

template<int BIAS, int RELU>
__global__ void __launch_bounds__(256)
tgemm2(const float* __restrict__ A, const float* __restrict__ B,
       const float* __restrict__ bias, float* __restrict__ C,
       int K, int lda, int ldb, int ldc) {
    constexpr int ABUF = 128 * ASTR;
    constexpr int BBUF = 32 * B2STR;

    extern __shared__ float smm[];
    float* sA = smm;
    float* sB = smm + 2 * ABUF;
    uint32_t* sAh = (uint32_t*)(sB + 2 * BBUF);
    uint32_t* sAl = sAh + 128 * APSTR;
    uint32_t* sBh = sAl + 128 * APSTR;
    uint32_t* sBl = sBh + 16 * BP2STR;

    int tid = threadIdx.x;
    int rowBase = blockIdx.y * 128;
    int colBase = blockIdx.x * 128;

    uint32_t sAaddr = (uint32_t)__cvta_generic_to_shared(sA);
    uint32_t sBaddr = (uint32_t)__cvta_generic_to_shared(sB);

    int ntiles = K >> 5;

    {
#pragma unroll
        for (int i = 0; i < 4; i++) {
            int idx = tid + i * 256;
            int r = idx >> 3, c = (idx & 7) * 4;
            cpa16(sAaddr + (uint32_t)(r * ASTR + c) * 4,
                  A + (size_t)(rowBase + r) * lda + c);
        }
#pragma unroll
        for (int i = 0; i < 4; i++) {
            int idx = tid + i * 256;
            int r = idx >> 5, c = (idx & 31) * 4;
            cpa16(sBaddr + (uint32_t)(r * B2STR + c) * 4,
                  B + (size_t)r * ldb + colBase + c);
        }
        asm volatile("cp.async.commit_group;\n");
    }

    float acc[4][4][4] = {};
    int lane = tid & 31, warp = tid >> 5;
    int wm = warp >> 2, wn = warp & 3;
    int g = lane >> 2, tg = lane & 3;

    for (int t = 0; t < ntiles; t++) {
        asm volatile("cp.async.wait_group 0;\n");
        __syncthreads();
        int cur = t & 1, nxt = cur ^ 1;

        if (t + 1 < ntiles) {
            int k0 = (t + 1) << 5;
#pragma unroll
            for (int i = 0; i < 4; i++) {
                int idx = tid + i * 256;
                int r = idx >> 3, c = (idx & 7) * 4;
                cpa16(sAaddr + (uint32_t)(nxt * ABUF + r * ASTR + c) * 4,
                      A + (size_t)(rowBase + r) * lda + k0 + c);
            }
#pragma unroll
            for (int i = 0; i < 4; i++) {
                int idx = tid + i * 256;
                int r = idx >> 5, c = (idx & 31) * 4;
                cpa16(sBaddr + (uint32_t)(nxt * BBUF + r * B2STR + c) * 4,
                      B + (size_t)(k0 + r) * ldb + colBase + c);
            }
            asm volatile("cp.async.commit_group;\n");
        }

        // cooperative split+pack
        {
            const float* cA = sA + cur * ABUF;
#pragma unroll
            for (int i = 0; i < 4; i++) {
                int idx = tid + i * 256;
                int r = idx >> 3, cg = idx & 7;
                float4 xa = *(const float4*)(cA + r * ASTR + 4 * cg);
                uint32_t h0, l0, h1, l1;
                split2pack(xa.x, xa.y, h0, l0);
                split2pack(xa.z, xa.w, h1, l1);
                *(uint2*)&sAh[r * APSTR + 2 * cg] = make_uint2(h0, h1);
                *(uint2*)&sAl[r * APSTR + 2 * cg] = make_uint2(l0, l1);
            }
            const float* cBs = sB + cur * BBUF;
#pragma unroll
            for (int i = 0; i < 2; i++) {
                int idx = tid + i * 256;
                int kp = idx >> 5, cg = idx & 31, c = 4 * cg;
                float4 b0 = *(const float4*)(cBs + (2 * kp)     * B2STR + c);
                float4 b1 = *(const float4*)(cBs + (2 * kp + 1) * B2STR + c);
                uint32_t h[4], l[4];
                split2pack(b0.x, b1.x, h[0], l[0]);
                split2pack(b0.y, b1.y, h[1], l[1]);
                split2pack(b0.z, b1.z, h[2], l[2]);
                split2pack(b0.w, b1.w, h[3], l[3]);
                *(uint4*)&sBh[kp * BP2STR + c] = make_uint4(h[0], h[1], h[2], h[3]);
                *(uint4*)&sBl[kp * BP2STR + c] = make_uint4(l[0], l[1], l[2], l[3]);
            }
        }
        __syncthreads();

#pragma unroll
        for (int kk = 0; kk < 2; kk++) {
            unsigned bh[4][2], bl[4][2];
#pragma unroll
            for (int nt = 0; nt < 4; nt++) {
                int nb = wn * 32 + nt * 8;
                bh[nt][0] = sBh[(8 * kk + tg)     * BP2STR + nb + g];
                bh[nt][1] = sBh[(8 * kk + tg + 4) * BP2STR + nb + g];
                bl[nt][0] = sBl[(8 * kk + tg)     * BP2STR + nb + g];
                bl[nt][1] = sBl[(8 * kk + tg + 4) * BP2STR + nb + g];
            }
#pragma unroll
            for (int mt = 0; mt < 4; mt++) {
                int mb = wm * 64 + mt * 16;
                unsigned ah[4], al[4];
                ah[0] = sAh[(mb + g)     * APSTR + 8 * kk + tg];
                ah[1] = sAh[(mb + 8 + g) * APSTR + 8 * kk + tg];
                ah[2] = sAh[(mb + g)     * APSTR + 8 * kk + tg + 4];
                ah[3] = sAh[(mb + 8 + g) * APSTR + 8 * kk + tg + 4];
                al[0] = sAl[(mb + g)     * APSTR + 8 * kk + tg];
                al[1] = sAl[(mb + 8 + g) * APSTR + 8 * kk + tg];
                al[2] = sAl[(mb + g)     * APSTR + 8 * kk + tg + 4];
                al[3] = sAl[(mb + 8 + g) * APSTR + 8 * kk + tg + 4];
#pragma unroll
                for (int nt = 0; nt < 4; nt++) {
                    mma_bf(acc[mt][nt], al, bh[nt]);
                    mma_bf(acc[mt][nt], ah, bl[nt]);
                    mma_bf(acc[mt][nt], ah, bh[nt]);
                }
            }
        }
        __syncthreads();
    }

#pragma unroll
    for (int mt = 0; mt < 4; mt++) {
#pragma unroll
        for (int nt = 0; nt < 4; nt++) {
            int r0 = rowBase + wm * 64 + mt * 16 + g;
            int c0 = colBase + wn * 32 + nt * 8 + 2 * tg;
            float bx = 0.f, by = 0.f;
            if (BIAS) { bx = bias[c0]; by = bias[c0 + 1]; }
            size_t o0 = (size_t)r0 * ldc + c0;
            size_t o1 = (size_t)(r0 + 8) * ldc + c0;
            float v0 = acc[mt][nt][0] + bx;
            float v1 = acc[mt][nt][1] + by;
            float v2 = acc[mt][nt][2] + bx;
            float v3 = acc[mt][nt][3] + by;
            if (RELU) {
                v0 = fmaxf(v0, 0.f); v1 = fmaxf(v1, 0.f);
                v2 = fmaxf(v2, 0.f); v3 = fmaxf(v3, 0.f);
            }
            C[o0] = v0; C[o0 + 1] = v1;
            C[o1] = v2; C[o1 + 1] = v3;
        }
    }
}

#define SMEM_T2 ((2 * (128 * ASTR) + 2 * (32 * B2STR) + 2 * (128 * APSTR) + 2 * (16 * BP2STR)) * 4)  // 108032

// ---------------------------------------------------------------------------
// MMA flash attention v6 (bf16x3, FA2 register softmax, 2-way split-KV)
// ---------------------------------------------------------------------------
#define QPSTR 36
#define KPSTR 36
#define VPSTR 72
#define FLASH_SMEM ((2 * 128 * QPSTR + 2 * 64 * KPSTR + 2 * 32 * VPSTR) * 4)

__global__ void __launch_bounds__(256)
flash_mma(const float* __restrict__ q, const float* __restrict__ k,
          const float* __restrict__ v, float* __restrict__ npart,
          float* __restrict__ smax, float* __restrict__ ssum) {
    extern __shared__ uint32_t smu[];
    uint32_t* sQh = smu;
    uint32_t* sQl = sQh + 128 * QPSTR;
    uint32_t* sKh = sQl + 128 * QPSTR;
    uint32_t* sKl = sKh + 64 * KPSTR;
    uint32_t* sVh = sKl + 64 * KPSTR;
    uint32_t* sVl = sVh + 32 * VPSTR;

    int qb = blockIdx.x * 128, h = blockIdx.y;
    int b = blockIdx.z >> 1, sp = blockIdx.z & 1;
    int tid = threadIdx.x, lane = tid & 31, warp = tid >> 5;
    int g = lane >> 2, tg = lane & 3;
    int mb = warp * 16;

    int ntile = (qb >> 6) + 2;
    int half = ntile - (ntile >> 1);
    int ktBeg = sp ? half : 0;
    int ktEnd = sp ? ntile : half;

    const float* qp = q + (size_t)(b * TT + qb) * DM + h * HSZ;
    for (int i = tid; i < 128 * 16; i += 256) {
        int r = i >> 4, cg = i & 15;
        float4 t = *(const float4*)(qp + (size_t)r * DM + 4 * cg);
        uint32_t h0, l0, h1, l1;
        split2pack(t.x * 0.125f, t.y * 0.125f, h0, l0);
        split2pack(t.z * 0.125f, t.w * 0.125f, h1, l1);
        *(uint2*)&sQh[r * QPSTR + 2 * cg] = make_uint2(h0, h1);
        *(uint2*)&sQl[r * QPSTR + 2 * cg] = make_uint2(l0, l1);
    }

    float accO[8][4] = {};
    float m0 = -INFINITY, m1 = -INFINITY, l0 = 0.f, l1 = 0.f;

    int rowg0 = qb + mb + g;
    int rowg1 = rowg0 + 8;

    for (int kt = ktBeg; kt < ktEnd; kt++) {
        __syncthreads();
        const float* kp = k + (size_t)(b * TT + kt * 64) * DM + h * HSZ;
        const float* vp = v + (size_t)(b * TT + kt * 64) * DM + h * HSZ;
        for (int i = tid; i < 64 * 16; i += 256) {
            int r = i >> 4, cg = i & 15;
            float4 tk = *(const float4*)(kp + (size_t)r * DM + 4 * cg);
            uint32_t h0, lo0, h1, lo1;
            split2pack(tk.x, tk.y, h0, lo0);
            split2pack(tk.z, tk.w, h1, lo1);
            *(uint2*)&sKh[r * KPSTR + 2 * cg] = make_uint2(h0, h1);
            *(uint2*)&sKl[r * KPSTR + 2 * cg] = make_uint2(lo0, lo1);
        }
        for (int i = tid; i < 32 * 16; i += 256) {
            int kpr = i >> 4, cg = i & 15, c = 4 * cg;
            float4 v0 = *(const float4*)(vp + (size_t)(2 * kpr)     * DM + c);
            float4 v1 = *(const float4*)(vp + (size_t)(2 * kpr + 1) * DM + c);
            uint32_t hh[4], ll[4];
            split2pack(v0.x, v1.x, hh[0], ll[0]);
            split2pack(v0.y, v1.y, hh[1], ll[1]);
            split2pack(v0.z, v1.z, hh[2], ll[2]);
            split2pack(v0.w, v1.w, hh[3], ll[3]);
            *(uint4*)&sVh[kpr * VPSTR + c] = make_uint4(hh[0], hh[1], hh[2], hh[3]);
            *(uint4*)&sVl[kpr * VPSTR + c] = make_uint4(ll[0], ll[1], ll[2], ll[3]);
        }
        __syncthreads();

        if (kt * 64 > qb + mb + 15) continue;

        float accS[8][4] = {};
#pragma unroll
        for (int kb = 0; kb < 4; kb++) {
            unsigned qh[4], ql_[4];
            qh[0]  = sQh[(mb + g)     * QPSTR + 8 * kb + tg];
            qh[1]  = sQh[(mb + 8 + g) * QPSTR + 8 * kb + tg];
            qh[2]  = sQh[(mb + g)     * QPSTR + 8 * kb + tg + 4];
            qh[3]  = sQh[(mb + 8 + g) * QPSTR + 8 * kb + tg + 4];
            ql_[0] = sQl[(mb + g)     * QPSTR + 8 * kb + tg];
            ql_[1] = sQl[(mb + 8 + g) * QPSTR + 8 * kb + tg];
            ql_[2] = sQl[(mb + g)     * QPSTR + 8 * kb + tg + 4];
            ql_[3] = sQl[(mb + 8 + g) * QPSTR + 8 * kb + tg + 4];
#pragma unroll
            for (int nt = 0; nt < 8; nt++) {
                int nb = nt * 8;
                unsigned bh[2], bl[2];
                bh[0] = sKh[(nb + g) * KPSTR + 8 * kb + tg];
                bh[1] = sKh[(nb + g) * KPSTR + 8 * kb + tg + 4];
                bl[0] = sKl[(nb + g) * KPSTR + 8 * kb + tg];
                bl[1] = sKl[(nb + g) * KPSTR + 8 * kb + tg + 4];
                mma_bf(accS[nt], ql_, bh);
                mma_bf(accS[nt], qh, bl);
                mma_bf(accS[nt], qh, bh);
            }
        }

        if (kt * 64 + 63 > rowg0) {
#pragma unroll
            for (int nt = 0; nt < 8; nt++) {
                int kc = kt * 64 + nt * 8 + 2 * tg;
                if (kc     > rowg0) accS[nt][0] = -INFINITY;
                if (kc + 1 > rowg0) accS[nt][1] = -INFINITY;
                if (kc     > rowg1) accS[nt][2] = -INFINITY;
                if (kc + 1 > rowg1) accS[nt][3] = -INFINITY;
            }
        }

        float mx0 = -INFINITY, mx1 = -INFINITY;
#pragma unroll
        for (int nt = 0; nt < 8; nt++) {
            mx0 = fmaxf(mx0, fmaxf(accS[nt][0], accS[nt][1]));
            mx1 = fmaxf(mx1, fmaxf(accS[nt][2], accS[nt][3]));
        }
        mx0 = fmaxf(mx0, __shfl_xor_sync(0xffffffffu, mx0, 1));
        mx0 = fmaxf(mx0, __shfl_xor_sync(0xffffffffu, mx0, 2));
        mx1 = fmaxf(mx1, __shfl_xor_sync(0xffffffffu, mx1, 1));
        mx1 = fmaxf(mx1, __shfl_xor_sync(0xffffffffu, mx1, 2));
        float nm0 = fmaxf(m0, mx0), nm1 = fmaxf(m1, mx1);
        float al0 = __expf(m0 - nm0), al1 = __expf(m1 - nm1);
        m0 = nm0; m1 = nm1;

        float su0 = 0.f, su1 = 0.f;
#pragma unroll
        for (int nt = 0; nt < 8; nt++) {
            accS[nt][0] = __expf(accS[nt][0] - nm0);
            accS[nt][1] = __expf(accS[nt][1] - nm0);
            accS[nt][2] = __expf(accS[nt][2] - nm1);
            accS[nt][3] = __expf(accS[nt][3] - nm1);
            su0 += accS[nt][0] + accS[nt][1];
            su1 += accS[nt][2] + accS[nt][3];
        }
        su0 += __shfl_xor_sync(0xffffffffu, su0, 1);
        su0 += __shfl_xor_sync(0xffffffffu, su0, 2);
        su1 += __shfl_xor_sync(0xffffffffu, su1, 1);
        su1 += __shfl_xor_sync(0xffffffffu, su1, 2);
        l0 = l0 * al0 + su0;
        l1 = l1 * al1 + su1;

#pragma unroll
        for (int nt = 0; nt < 8; nt++) {
            accO[nt][0] *= al0; accO[nt][1] *= al0;
            accO[nt][2] *= al1; accO[nt][3] *= al1;
        }

#pragma unroll
        for (int kk = 0; kk < 4; kk++) {
            unsigned ph[4], pl_[4];
            split2pack(accS[2 * kk][0],     accS[2 * kk][1],     ph[0], pl_[0]);
            split2pack(accS[2 * kk][2],     accS[2 * kk][3],     ph[1], pl_[1]);
            split2pack(accS[2 * kk + 1][0], accS[2 * kk + 1][1], ph[2], pl_[2]);
            split2pack(accS[2 * kk + 1][2], accS[2 * kk + 1][3], ph[3], pl_[3]);
#pragma unroll
            for (int nt = 0; nt < 8; nt++) {
                int nb = nt * 8;
                unsigned bh[2], bl[2];
                bh[0] = sVh[(8 * kk + tg)     * VPSTR + nb + g];
                bh[1] = sVh[(8 * kk + tg + 4) * VPSTR + nb + g];
                bl[0] = sVl[(8 * kk + tg)     * VPSTR + nb + g];
                bl[1] = sVl[(8 * kk + tg + 4) * VPSTR + nb + g];
                mma_bf(accO[nt], pl_, bh);
                mma_bf(accO[nt], ph, bl);
                mma_bf(accO[nt], ph, bh);
            }
        }
    }

    int n0 = b * TT + rowg0;
    int n1 = n0 + 8;
    float* np = npart + (size_t)sp * NTOK * DM + (size_t)n0 * DM + h * HSZ;
#pragma unroll
    for (int nt = 0; nt < 8; nt++) {
        int c0 = nt * 8 + 2 * tg;
        np[c0]     = accO[nt][0];
        np[c0 + 1] = accO[nt][1];
        np[(size_t)8 * DM + c0]     = accO[nt][2];
        np[(size_t)8 * DM + c0 + 1] = accO[nt][3];
    }
    if (tg == 0) {
        smax[((size_t)sp * NTOK + n0) * NH + h] = m0;
        ssum[((size_t)sp * NTOK + n0) * NH + h] = l0;
        smax[((size_t)sp * NTOK + n1) * NH + h] = m1;
        ssum[((size_t)sp * NTOK + n1) * NH + h] = l1;
    }
}

// ---------------------------------------------------------------------------
__global__ void merge_kernel(const float* __restrict__ npart,
                             const float* __restrict__ smax,
                             const float* __restrict__ ssum,
                             float* __restrict__ out) {
    int i = blockIdx.x * blockDim.x + threadIdx.x;
    if (i >= NTOK * DM / 4) return;
    int n = i / (DM / 4);
    int c4 = i % (DM / 4);
    int h = (c4 * 4) / HSZ;

    float m0 = smax[(size_t)n * NH + h];
    float m1 = smax[((size_t)NTOK + n) * NH + h];
    float l0 = ssum[(size_t)n * NH + h];
    float l1 = ssum[((size_t)NTOK + n) * NH + h];
    float m = fmaxf(m0, m1);
    float w0 = __expf(m0 - m), w1 = __expf(m1 - m);
    float inv = 1.0f / (l0 * w0 + l1 * w1);

    float4 a = ((const float4*)npart)[i];
    float4 bq = ((const float4*)(npart + (size_t)NTOK * DM))[i];
    float4 o;
    o.x = (a.x * w0 + bq.x * w1) * inv;
    o.y = (a.y * w0 + bq.y * w1) * inv;
    o.z = (a.z * w0 + bq.z * w1) * inv;
    o.w = (a.w * w0 + bq.w * w1) * inv;
    ((float4*)out)[i] = o;
}

// ---------------------------------------------------------------------------
__global__ void zero_kernel(float* red) { red[0] = 0.f; red[1] = 0.f; }

__global__ void loss_kernel(const float* __restrict__ logits, const int* __restrict__ tgt,
                            float* __restrict__ red) {
    int r = blockIdx.x;
    int tid = threadIdx.x;
    int warp = tid >> 5, lane = tid & 31;
    const float* row = logits + (size_t)r * VOC;
    __shared__ float rbuf[8];

    float lmax = -INFINITY;
    for (int c = tid; c < VOC; c += 256) lmax = fmaxf(lmax, row[c]);
    lmax = warpMax(lmax);
    if (lane == 0) rbuf[warp] = lmax;
    __syncthreads();
    float gmax = -INFINITY;
#pragma unroll
    for (int w = 0; w < 8; w++) gmax = fmaxf(gmax, rbuf[w]);
    __syncthreads();

    float lsum = 0.f;
    for (int c = tid; c < VOC; c += 256) lsum += __expf(row[c] - gmax);
    lsum = warpSum(lsum);
    if (lane == 0) rbuf[warp] = lsum;
    __syncthreads();
    if (tid == 0) {
        float gsum = 0.f;
#pragma unroll
        for (int w = 0; w < 8; w++) gsum += rbuf[w];
        int tg = tgt[r];
        float lp = row[tg] - gmax - logf(gsum);
        float m = (tg != 0) ? 1.0f : 0.0f;
        atomicAdd(&red[0], -lp * m);
        atomicAdd(&red[1], m);
    }
}

__global__ void finalize_kernel(const float* __restrict__ red, float* __restrict__ outp) {
    outp[0] = red[0] / red[1];
}

// ---------------------------------------------------------------------------
extern "C" void kernel_launch(void* const* d_in, const int* in_sizes, int n_in,
                              void* d_out, int out_size) {
    const int*   toks = (const int*)d_in[0];
    const int*   tgts = (const int*)d_in[1];
    const float* temb = (const float*)d_in[2];
    const float* pemb = (const float*)d_in[3];
    const float* Wq   = (const float*)d_in[4];
    const float* Wk   = (const float*)d_in[5];
    const float* Wv   = (const float*)d_in[6];
    const float* Wo   = (const float*)d_in[7];
    const float* bo   = (const float*)d_in[8];
    const float* ln1g = (const float*)d_in[9];
    const float* ln1b = (const float*)d_in[10];
    const float* ln2g = (const float*)d_in[11];
    const float* ln2b = (const float*)d_in[12];
    const float* W1   = (const float*)d_in[13];
    const float* b1   = (const float*)d_in[14];
    const float* W2   = (const float*)d_in[15];
    const float* b2   = (const float*)d_in[16];
    const float* lnfg = (const float*)d_in[17];
    const float* lnfb = (const float*)d_in[18];
    const float* Wout = (const float*)d_in[19];
    const float* bout = (const float*)d_in[20];

    float *x, *h, *q, *k, *v, *a, *ff, *red, *lfb, *part, *sm_, *sl_;
    cudaGetSymbolAddress((void**)&x,    g_x);
    cudaGetSymbolAddress((void**)&h,    g_h);
    cudaGetSymbolAddress((void**)&q,    g_q);
    cudaGetSymbolAddress((void**)&k,    g_k);
    cudaGetSymbolAddress((void**)&v,    g_v);
    cudaGetSymbolAddress((void**)&a,    g_a);
    cudaGetSymbolAddress((void**)&ff,   g_ff);
    cudaGetSymbolAddress((void**)&red,  g_red);
    cudaGetSymbolAddress((void**)&lfb,  g_logits_fb);
    cudaGetSymbolAddress((void**)&part, g_part);
    cudaGetSymbolAddress((void**)&sm_,  g_sm);
    cudaGetSymbolAddress((void**)&sl_,  g_sl);

    cudaFuncSetAttribute((const void*)tgemm<1,0,0,0,1>, cudaFuncAttributeMaxDynamicSharedMemorySize, SMEM_MT1);
    cudaFuncSetAttribute((const void*)tgemm<1,1,1,0,0>, cudaFuncAttributeMaxDynamicSharedMemorySize, SMEM_MT1);
    cudaFuncSetAttribute((const void*)tgemm2<1,1>,      cudaFuncAttributeMaxDynamicSharedMemorySize, SMEM_T2);
    cudaFuncSetAttribute((const void*)tgemm2<1,0>,      cudaFuncAttributeMaxDynamicSharedMemorySize, SMEM_T2);
    cudaFuncSetAttribute((const void*)flash_mma,        cudaFuncAttributeMaxDynamicSharedMemorySize, FLASH_SMEM);

    embed_kernel<<<(NTOK * DM / 4 + 255) / 256, 256>>>(toks, temb, pemb, x);

    for (int l = 0; l < NL; l++) {
        ln_kernel<<<NTOK, 128>>>(x, h, ln1g + l * DM, ln1b + l * DM);

        tgemm<1,0,0,0,1><<<dim3(1, NTOK / 64, 24), 256, SMEM_MT1>>>(
            h,
            Wq + (size_t)l * NH * DM * HSZ,
            Wk + (size_t)l * NH * DM * HSZ,
            Wv + (size_t)l * NH * DM * HSZ,
            nullptr, nullptr,
            q, k, v,
            DM, DM, HSZ, DM, (long)DM * HSZ, HSZ);

        flash_mma<<<dim3(TT / 128, NH, BT * 2), 256, FLASH_SMEM>>>(q, k, v, part, sm_, sl_);
        merge_kernel<<<(NTOK * DM / 4 + 255) / 256, 256>>>(part, sm_, sl_, a);

        tgemm<1,1,1,0,0><<<dim3(DM / 64, NTOK / 64, 1), 256, SMEM_MT1>>>(
            a, Wo + (size_t)l * DM * DM, nullptr, nullptr,
            bo + l * DM, x, x, nullptr, nullptr,
            DM, DM, DM, DM, 0, 0);

        ln_kernel<<<NTOK, 128>>>(x, h, ln2g + l * DM, ln2b + l * DM);

        // FF1 + bias + relu (128x128 tiles)
        tgemm2<1,1><<<dim3(FFD / 128, NTOK / 128), 256, SMEM_T2>>>(
            h, W1 + (size_t)l * DM * FFD, b1 + (size_t)l * FFD, ff,
            DM, DM, FFD, FFD);
        // FF2 + bias + residual
        tgemm<1,1,1,0,0><<<dim3(DM / 64, NTOK / 64, 1), 256, SMEM_MT1>>>(
            ff, W2 + (size_t)l * FFD * DM, nullptr, nullptr,
            b2 + l * DM, x, x, nullptr, nullptr,
            FFD, FFD, DM, DM, 0, 0);
    }

    ln_kernel<<<NTOK, 128>>>(x, h, lnfg, lnfb);

    const long logitsElems = (long)NTOK * VOC;
    float* logits = ((long)out_size >= logitsElems) ? (float*)d_out : lfb;

    // logits GEMM (128x128 tiles)
    tgemm2<1,0><<<dim3(VOC / 128, NTOK / 128), 256, SMEM_T2>>>(
        h, Wout, bout, logits, DM, DM, VOC, VOC);

    if ((long)out_size != logitsElems) {
        zero_kernel<<<1, 1>>>(red);
        loss_kernel<<<NTOK, 256>>>(logits, tgts, red);
        float* lossOut;
        if ((long)out_size > logitsElems)
            lossOut = (float*)d_out + logitsElems;
        else
            lossOut = (float*)d_out + (out_size - 1);
        finalize_kernel<<<1, 1>>>(red, lossOut);
    }
}

// round 16
// speedup vs baseline: 1.0739x; 1.0739x over previous
#include <cuda_runtime.h>
#include <cuda_bf16.h>
#include <math.h>
#include <stdint.h>

// Model dims
#define BT   2
#define TT   2048
#define NTOK 4096
#define DM   512
#define NH   8
#define HSZ  64
#define FFD  2048
#define NL   6
#define VOC  32000

// Scratch
__device__ float g_x [NTOK * DM];
__device__ float g_h [NTOK * DM];
__device__ float g_q [NTOK * DM];
__device__ float g_k [NTOK * DM];
__device__ float g_v [NTOK * DM];
__device__ float g_a [NTOK * DM];
__device__ float g_ff[NTOK * FFD];
__device__ float g_red[2];
__device__ float g_part[2 * NTOK * DM];
__device__ float g_sm[2 * NTOK * NH];
__device__ float g_sl[2 * NTOK * NH];
__device__ float g_logits_fb[(size_t)NTOK * VOC];

// ---------------------------------------------------------------------------
__device__ __forceinline__ float warpSum(float v) {
#pragma unroll
    for (int o = 16; o > 0; o >>= 1) v += __shfl_xor_sync(0xffffffffu, v, o);
    return v;
}
__device__ __forceinline__ float warpMax(float v) {
#pragma unroll
    for (int o = 16; o > 0; o >>= 1) v = fmaxf(v, __shfl_xor_sync(0xffffffffu, v, o));
    return v;
}

// ---------------------------------------------------------------------------
__global__ void embed_kernel(const int* __restrict__ toks,
                             const float* __restrict__ temb,
                             const float* __restrict__ pemb,
                             float* __restrict__ x) {
    int i = blockIdx.x * blockDim.x + threadIdx.x;
    if (i >= NTOK * DM / 4) return;
    int n  = i / (DM / 4);
    int c  = i % (DM / 4);
    int tk = toks[n];
    int t  = n % TT;
    float4 a = ((const float4*)temb)[(size_t)tk * (DM / 4) + c];
    float4 p = ((const float4*)pemb)[(size_t)t  * (DM / 4) + c];
    float4 r;
    r.x = a.x + p.x; r.y = a.y + p.y; r.z = a.z + p.z; r.w = a.w + p.w;
    ((float4*)x)[i] = r;
}

// ---------------------------------------------------------------------------
__global__ void ln_kernel(const float* __restrict__ in, float* __restrict__ out,
                          const float* __restrict__ gamma, const float* __restrict__ beta) {
    int row = blockIdx.x;
    int tid = threadIdx.x;
    const float4 v4 = ((const float4*)(in + (size_t)row * DM))[tid];
    float s  = v4.x + v4.y + v4.z + v4.w;
    float s2 = v4.x * v4.x + v4.y * v4.y + v4.z * v4.z + v4.w * v4.w;

    __shared__ float rs[4], rs2[4];
    int warp = tid >> 5, lane = tid & 31;
    s = warpSum(s); s2 = warpSum(s2);
    if (lane == 0) { rs[warp] = s; rs2[warp] = s2; }
    __syncthreads();
    float ts = 0.f, ts2 = 0.f;
#pragma unroll
    for (int w = 0; w < 4; w++) { ts += rs[w]; ts2 += rs2[w]; }
    float mean = ts * (1.0f / DM);
    float var  = ts2 * (1.0f / DM) - mean * mean;
    float rstd = rsqrtf(var + 1e-5f);

    float4 g4 = ((const float4*)gamma)[tid];
    float4 b4 = ((const float4*)beta)[tid];
    float4 o;
    o.x = (v4.x - mean) * rstd * g4.x + b4.x;
    o.y = (v4.y - mean) * rstd * g4.y + b4.y;
    o.z = (v4.z - mean) * rstd * g4.z + b4.z;
    o.w = (v4.w - mean) * rstd * g4.w + b4.w;
    ((float4*)(out + (size_t)row * DM))[tid] = o;
}

// ---------------------------------------------------------------------------
// bf16x3 helpers
// ---------------------------------------------------------------------------
__device__ __forceinline__ void cpa16(uint32_t s, const void* g) {
    asm volatile("cp.async.cg.shared.global [%0], [%1], 16;\n" :: "r"(s), "l"(g));
}

__device__ __forceinline__ uint32_t bfb(float x) {
    return (uint32_t)__bfloat16_as_ushort(__float2bfloat16(x));
}
__device__ __forceinline__ void split2pack(float e, float o, uint32_t& hp, uint32_t& lp) {
    uint32_t he = bfb(e), ho = bfb(o);
    float re = e - __uint_as_float(he << 16);
    float ro = o - __uint_as_float(ho << 16);
    hp = he | (ho << 16);
    lp = bfb(re) | (bfb(ro) << 16);
}

__device__ __forceinline__ void mma_bf(float (&c)[4], const unsigned (&A)[4], const unsigned (&B)[2]) {
    asm volatile(
        "mma.sync.aligned.m16n8k16.row.col.f32.bf16.bf16.f32 "
        "{%0,%1,%2,%3}, {%4,%5,%6,%7}, {%8,%9}, {%0,%1,%2,%3};\n"
        : "+f"(c[0]), "+f"(c[1]), "+f"(c[2]), "+f"(c[3])
        : "r"(A[0]), "r"(A[1]), "r"(A[2]), "r"(A[3]), "r"(B[0]), "r"(B[1]));
}

// ---------------------------------------------------------------------------
// bf16x3 tensor-core GEMM, BN=64 (all GEMMs; R14 configuration)
// ---------------------------------------------------------------------------
#define ASTR 36
#define BSTR 72
#define APSTR 20
#define BPSTR 72

template<int MT, int BIAS, int RES, int RELU, int QKV>
__global__ void __launch_bounds__(256)
tgemm(const float* __restrict__ A,
      const float* __restrict__ B0, const float* __restrict__ B1, const float* __restrict__ B2,
      const float* __restrict__ bias, const float* __restrict__ res,
      float* __restrict__ C0, float* __restrict__ C1, float* __restrict__ C2,
      int K, int lda, int ldb, int ldc, long bz, long cz) {
    constexpr int BM   = MT * 64;
    constexpr int ABUF = BM * ASTR;
    constexpr int BBUF = 32 * BSTR;

    extern __shared__ float smm[];
    float* sA = smm;
    float* sB = smm + 2 * ABUF;
    uint32_t* sAh = (uint32_t*)(sB + 2 * BBUF);
    uint32_t* sAl = sAh + BM * APSTR;
    uint32_t* sBh = sAl + BM * APSTR;
    uint32_t* sBl = sBh + 16 * BPSTR;

    const float* B;
    float* C;
    if (QKV) {
        int z = blockIdx.z, sel = z >> 3, head = z & 7;
        const float* Bp = (sel == 0) ? B0 : (sel == 1) ? B1 : B2;
        float*       Cp = (sel == 0) ? C0 : (sel == 1) ? C1 : C2;
        B = Bp + (long)head * bz;
        C = Cp + (long)head * cz;
    } else {
        B = B0 + (long)blockIdx.z * bz;
        C = C0 + (long)blockIdx.z * cz;
    }

    int tid = threadIdx.x;
    int rowBase = blockIdx.y * BM;
    int colBase = blockIdx.x * 64;

    uint32_t sAaddr = (uint32_t)__cvta_generic_to_shared(sA);
    uint32_t sBaddr = (uint32_t)__cvta_generic_to_shared(sB);

    int ntiles = K >> 5;

    {
#pragma unroll
        for (int i = 0; i < 2 * MT; i++) {
            int idx = tid + i * 256;
            int r = idx >> 3, c = (idx & 7) * 4;
            cpa16(sAaddr + (uint32_t)(r * ASTR + c) * 4,
                  A + (size_t)(rowBase + r) * lda + c);
        }
#pragma unroll
        for (int i = 0; i < 2; i++) {
            int idx = tid + i * 256;
            int r = idx >> 4, c = (idx & 15) * 4;
            cpa16(sBaddr + (uint32_t)(r * BSTR + c) * 4,
                  B + (size_t)r * ldb + colBase + c);
        }
        asm volatile("cp.async.commit_group;\n");
    }

    float acc[MT][4][4] = {};
    int lane = tid & 31, warp = tid >> 5;
    int wm = warp >> 1, wn = warp & 1;
    int g = lane >> 2, tg = lane & 3;

    for (int t = 0; t < ntiles; t++) {
        asm volatile("cp.async.wait_group 0;\n");
        __syncthreads();
        int cur = t & 1, nxt = cur ^ 1;

        if (t + 1 < ntiles) {
            int k0 = (t + 1) << 5;
#pragma unroll
            for (int i = 0; i < 2 * MT; i++) {
                int idx = tid + i * 256;
                int r = idx >> 3, c = (idx & 7) * 4;
                cpa16(sAaddr + (uint32_t)(nxt * ABUF + r * ASTR + c) * 4,
                      A + (size_t)(rowBase + r) * lda + k0 + c);
            }
#pragma unroll
            for (int i = 0; i < 2; i++) {
                int idx = tid + i * 256;
                int r = idx >> 4, c = (idx & 15) * 4;
                cpa16(sBaddr + (uint32_t)(nxt * BBUF + r * BSTR + c) * 4,
                      B + (size_t)(k0 + r) * ldb + colBase + c);
            }
            asm volatile("cp.async.commit_group;\n");
        }

        {
            const float* cA = sA + cur * ABUF;
#pragma unroll
            for (int i = 0; i < 2 * MT; i++) {
                int idx = tid + i * 256;
                int r = idx >> 3, cg = idx & 7;
                float4 xa = *(const float4*)(cA + r * ASTR + 4 * cg);
                uint32_t h0, l0, h1, l1;
                split2pack(xa.x, xa.y, h0, l0);
                split2pack(xa.z, xa.w, h1, l1);
                *(uint2*)&sAh[r * APSTR + 2 * cg] = make_uint2(h0, h1);
                *(uint2*)&sAl[r * APSTR + 2 * cg] = make_uint2(l0, l1);
            }
            const float* cBs = sB + cur * BBUF;
            int kp = tid >> 4, cg = tid & 15, c = 4 * cg;
            float4 b0 = *(const float4*)(cBs + (2 * kp)     * BSTR + c);
            float4 b1 = *(const float4*)(cBs + (2 * kp + 1) * BSTR + c);
            uint32_t h[4], l[4];
            split2pack(b0.x, b1.x, h[0], l[0]);
            split2pack(b0.y, b1.y, h[1], l[1]);
            split2pack(b0.z, b1.z, h[2], l[2]);
            split2pack(b0.w, b1.w, h[3], l[3]);
            *(uint4*)&sBh[kp * BPSTR + c] = make_uint4(h[0], h[1], h[2], h[3]);
            *(uint4*)&sBl[kp * BPSTR + c] = make_uint4(l[0], l[1], l[2], l[3]);
        }
        __syncthreads();

#pragma unroll
        for (int kk = 0; kk < 2; kk++) {
            unsigned ah[MT][4], al[MT][4];
#pragma unroll
            for (int mt = 0; mt < MT; mt++) {
                int mb = wm * (MT * 16) + mt * 16;
                ah[mt][0] = sAh[(mb + g)     * APSTR + 8 * kk + tg];
                ah[mt][1] = sAh[(mb + 8 + g) * APSTR + 8 * kk + tg];
                ah[mt][2] = sAh[(mb + g)     * APSTR + 8 * kk + tg + 4];
                ah[mt][3] = sAh[(mb + 8 + g) * APSTR + 8 * kk + tg + 4];
                al[mt][0] = sAl[(mb + g)     * APSTR + 8 * kk + tg];
                al[mt][1] = sAl[(mb + 8 + g) * APSTR + 8 * kk + tg];
                al[mt][2] = sAl[(mb + g)     * APSTR + 8 * kk + tg + 4];
                al[mt][3] = sAl[(mb + 8 + g) * APSTR + 8 * kk + tg + 4];
            }
#pragma unroll
            for (int nt = 0; nt < 4; nt++) {
                int nb = wn * 32 + nt * 8;
                unsigned bh[2], bl[2];
                bh[0] = sBh[(8 * kk + tg)     * BPSTR + nb + g];
                bh[1] = sBh[(8 * kk + tg + 4) * BPSTR + nb + g];
                bl[0] = sBl[(8 * kk + tg)     * BPSTR + nb + g];
                bl[1] = sBl[(8 * kk + tg + 4) * BPSTR + nb + g];
#pragma unroll
                for (int mt = 0; mt < MT; mt++) {
                    mma_bf(acc[mt][nt], al[mt], bh);
                    mma_bf(acc[mt][nt], ah[mt], bl);
                    mma_bf(acc[mt][nt], ah[mt], bh);
                }
            }
        }
        __syncthreads();
    }

#pragma unroll
    for (int mt = 0; mt < MT; mt++) {
#pragma unroll
        for (int nt = 0; nt < 4; nt++) {
            int r0 = rowBase + wm * (MT * 16) + mt * 16 + g;
            int c0 = colBase + wn * 32 + nt * 8 + 2 * tg;
            float bx = 0.f, by = 0.f;
            if (BIAS) { bx = bias[c0]; by = bias[c0 + 1]; }
            size_t o0 = (size_t)r0 * ldc + c0;
            size_t o1 = (size_t)(r0 + 8) * ldc + c0;
            float v0 = acc[mt][nt][0] + bx;
            float v1 = acc[mt][nt][1] + by;
            float v2 = acc[mt][nt][2] + bx;
            float v3 = acc[mt][nt][3] + by;
            if (RES) {
                v0 += res[o0]; v1 += res[o0 + 1];
                v2 += res[o1]; v3 += res[o1 + 1];
            }
            if (RELU) {
                v0 = fmaxf(v0, 0.f); v1 = fmaxf(v1, 0.f);
                v2 = fmaxf(v2, 0.f); v3 = fmaxf(v3, 0.f);
            }
            C[o0] = v0; C[o0 + 1] = v1;
            C[o1] = v2; C[o1 + 1] = v3;
        }
    }
}

#define SMEM_MT1 ((2 * (64  * ASTR) + 2 * (32 * BSTR) + 2 * (64  * APSTR) + 2 * (16 * BPSTR)) * 4)
#define SMEM_MT2 ((2 * (128 * ASTR) + 2 * (32 * BSTR) + 2 * (128 * APSTR) + 2 * (16 * BPSTR)) * 4)

// ---------------------------------------------------------------------------
// MMA flash attention v7 (bf16x3, FA2 register softmax, 2-way split-KV,
// cp.async-pipelined raw K/V staging: tile kt+1 loads overlap tile kt MMAs).
// ---------------------------------------------------------------------------
#define QPSTR 36
#define KPSTR 36
#define VPSTR 72
#define RSTR  68
#define FLASH_SMEM ((2 * 128 * QPSTR + 2 * 64 * KPSTR + 2 * 32 * VPSTR + 2 * 64 * RSTR) * 4)  // 108544

__global__ void __launch_bounds__(256)
flash_mma(const float* __restrict__ q, const float* __restrict__ k,
          const float* __restrict__ v, float* __restrict__ npart,
          float* __restrict__ smax, float* __restrict__ ssum) {
    extern __shared__ uint32_t smu[];
    uint32_t* sQh = smu;
    uint32_t* sQl = sQh + 128 * QPSTR;
    uint32_t* sKh = sQl + 128 * QPSTR;
    uint32_t* sKl = sKh + 64 * KPSTR;
    uint32_t* sVh = sKl + 64 * KPSTR;
    uint32_t* sVl = sVh + 32 * VPSTR;
    float*    rK  = (float*)(sVl + 32 * VPSTR);   // raw K staging 64 x RSTR
    float*    rV  = rK + 64 * RSTR;               // raw V staging 64 x RSTR

    int qb = blockIdx.x * 128, h = blockIdx.y;
    int b = blockIdx.z >> 1, sp = blockIdx.z & 1;
    int tid = threadIdx.x, lane = tid & 31, warp = tid >> 5;
    int g = lane >> 2, tg = lane & 3;
    int mb = warp * 16;

    int ntile = (qb >> 6) + 2;
    int half = ntile - (ntile >> 1);
    int ktBeg = sp ? half : 0;
    int ktEnd = sp ? ntile : half;

    uint32_t rKaddr = (uint32_t)__cvta_generic_to_shared(rK);
    uint32_t rVaddr = (uint32_t)__cvta_generic_to_shared(rV);
    const float* kbase = k + (size_t)(b * TT) * DM + h * HSZ;
    const float* vbase = v + (size_t)(b * TT) * DM + h * HSZ;

    // prologue: issue raw K/V loads for first tile
    {
        const float* kp = kbase + (size_t)(ktBeg * 64) * DM;
        const float* vp = vbase + (size_t)(ktBeg * 64) * DM;
#pragma unroll
        for (int i = 0; i < 4; i++) {
            int idx = tid + i * 256;
            int r = idx >> 4, c = (idx & 15) * 4;
            cpa16(rKaddr + (uint32_t)(r * RSTR + c) * 4, kp + (size_t)r * DM + c);
            cpa16(rVaddr + (uint32_t)(r * RSTR + c) * 4, vp + (size_t)r * DM + c);
        }
        asm volatile("cp.async.commit_group;\n");
    }

    // cooperative Q load+split+pack (scaled) — overlaps with the cp.async above
    const float* qp = q + (size_t)(b * TT + qb) * DM + h * HSZ;
    for (int i = tid; i < 128 * 16; i += 256) {
        int r = i >> 4, cg = i & 15;
        float4 t = *(const float4*)(qp + (size_t)r * DM + 4 * cg);
        uint32_t h0, l0, h1, l1;
        split2pack(t.x * 0.125f, t.y * 0.125f, h0, l0);
        split2pack(t.z * 0.125f, t.w * 0.125f, h1, l1);
        *(uint2*)&sQh[r * QPSTR + 2 * cg] = make_uint2(h0, h1);
        *(uint2*)&sQl[r * QPSTR + 2 * cg] = make_uint2(l0, l1);
    }

    float accO[8][4] = {};
    float m0 = -INFINITY, m1 = -INFINITY, l0 = 0.f, l1 = 0.f;

    int rowg0 = qb + mb + g;
    int rowg1 = rowg0 + 8;

    for (int kt = ktBeg; kt < ktEnd; kt++) {
        asm volatile("cp.async.wait_group 0;\n");
        __syncthreads();   // raw tile landed; prior compute done reading planes

        // split raw -> packed hi/lo planes
        for (int i = tid; i < 64 * 16; i += 256) {
            int r = i >> 4, cg = i & 15;
            float4 tk = *(const float4*)(rK + r * RSTR + 4 * cg);
            uint32_t h0, lo0, h1, lo1;
            split2pack(tk.x, tk.y, h0, lo0);
            split2pack(tk.z, tk.w, h1, lo1);
            *(uint2*)&sKh[r * KPSTR + 2 * cg] = make_uint2(h0, h1);
            *(uint2*)&sKl[r * KPSTR + 2 * cg] = make_uint2(lo0, lo1);
        }
        for (int i = tid; i < 32 * 16; i += 256) {
            int kpr = i >> 4, cg = i & 15, c = 4 * cg;
            float4 v0 = *(const float4*)(rV + (2 * kpr)     * RSTR + c);
            float4 v1 = *(const float4*)(rV + (2 * kpr + 1) * RSTR + c);
            uint32_t hh[4], ll[4];
            split2pack(v0.x, v1.x, hh[0], ll[0]);
            split2pack(v0.y, v1.y, hh[1], ll[1]);
            split2pack(v0.z, v1.z, hh[2], ll[2]);
            split2pack(v0.w, v1.w, hh[3], ll[3]);
            *(uint4*)&sVh[kpr * VPSTR + c] = make_uint4(hh[0], hh[1], hh[2], hh[3]);
            *(uint4*)&sVl[kpr * VPSTR + c] = make_uint4(ll[0], ll[1], ll[2], ll[3]);
        }
        __syncthreads();   // planes ready; raw buffer now dead

        // issue next tile's raw loads (overlaps with compute below)
        if (kt + 1 < ktEnd) {
            const float* kp = kbase + (size_t)((kt + 1) * 64) * DM;
            const float* vp = vbase + (size_t)((kt + 1) * 64) * DM;
#pragma unroll
            for (int i = 0; i < 4; i++) {
                int idx = tid + i * 256;
                int r = idx >> 4, c = (idx & 15) * 4;
                cpa16(rKaddr + (uint32_t)(r * RSTR + c) * 4, kp + (size_t)r * DM + c);
                cpa16(rVaddr + (uint32_t)(r * RSTR + c) * 4, vp + (size_t)r * DM + c);
            }
            asm volatile("cp.async.commit_group;\n");
        }

        if (kt * 64 > qb + mb + 15) continue;   // tile fully masked for this warp

        // ---- S = Q @ K^T ----
        float accS[8][4] = {};
#pragma unroll
        for (int kb = 0; kb < 4; kb++) {
            unsigned qh[4], ql_[4];
            qh[0]  = sQh[(mb + g)     * QPSTR + 8 * kb + tg];
            qh[1]  = sQh[(mb + 8 + g) * QPSTR + 8 * kb + tg];
            qh[2]  = sQh[(mb + g)     * QPSTR + 8 * kb + tg + 4];
            qh[3]  = sQh[(mb + 8 + g) * QPSTR + 8 * kb + tg + 4];
            ql_[0] = sQl[(mb + g)     * QPSTR + 8 * kb + tg];
            ql_[1] = sQl[(mb + 8 + g) * QPSTR + 8 * kb + tg];
            ql_[2] = sQl[(mb + g)     * QPSTR + 8 * kb + tg + 4];
            ql_[3] = sQl[(mb + 8 + g) * QPSTR + 8 * kb + tg + 4];
#pragma unroll
            for (int nt = 0; nt < 8; nt++) {
                int nb = nt * 8;
                unsigned bh[2], bl[2];
                bh[0] = sKh[(nb + g) * KPSTR + 8 * kb + tg];
                bh[1] = sKh[(nb + g) * KPSTR + 8 * kb + tg + 4];
                bl[0] = sKl[(nb + g) * KPSTR + 8 * kb + tg];
                bl[1] = sKl[(nb + g) * KPSTR + 8 * kb + tg + 4];
                mma_bf(accS[nt], ql_, bh);
                mma_bf(accS[nt], qh, bl);
                mma_bf(accS[nt], qh, bh);
            }
        }

        if (kt * 64 + 63 > rowg0) {
#pragma unroll
            for (int nt = 0; nt < 8; nt++) {
                int kc = kt * 64 + nt * 8 + 2 * tg;
                if (kc     > rowg0) accS[nt][0] = -INFINITY;
                if (kc + 1 > rowg0) accS[nt][1] = -INFINITY;
                if (kc     > rowg1) accS[nt][2] = -INFINITY;
                if (kc + 1 > rowg1) accS[nt][3] = -INFINITY;
            }
        }

        // ---- register softmax ----
        float mx0 = -INFINITY, mx1 = -INFINITY;
#pragma unroll
        for (int nt = 0; nt < 8; nt++) {
            mx0 = fmaxf(mx0, fmaxf(accS[nt][0], accS[nt][1]));
            mx1 = fmaxf(mx1, fmaxf(accS[nt][2], accS[nt][3]));
        }
        mx0 = fmaxf(mx0, __shfl_xor_sync(0xffffffffu, mx0, 1));
        mx0 = fmaxf(mx0, __shfl_xor_sync(0xffffffffu, mx0, 2));
        mx1 = fmaxf(mx1, __shfl_xor_sync(0xffffffffu, mx1, 1));
        mx1 = fmaxf(mx1, __shfl_xor_sync(0xffffffffu, mx1, 2));
        float nm0 = fmaxf(m0, mx0), nm1 = fmaxf(m1, mx1);
        float al0 = __expf(m0 - nm0), al1 = __expf(m1 - nm1);
        m0 = nm0; m1 = nm1;

        float su0 = 0.f, su1 = 0.f;
#pragma unroll
        for (int nt = 0; nt < 8; nt++) {
            accS[nt][0] = __expf(accS[nt][0] - nm0);
            accS[nt][1] = __expf(accS[nt][1] - nm0);
            accS[nt][2] = __expf(accS[nt][2] - nm1);
            accS[nt][3] = __expf(accS[nt][3] - nm1);
            su0 += accS[nt][0] + accS[nt][1];
            su1 += accS[nt][2] + accS[nt][3];
        }
        su0 += __shfl_xor_sync(0xffffffffu, su0, 1);
        su0 += __shfl_xor_sync(0xffffffffu, su0, 2);
        su1 += __shfl_xor_sync(0xffffffffu, su1, 1);
        su1 += __shfl_xor_sync(0xffffffffu, su1, 2);
        l0 = l0 * al0 + su0;
        l1 = l1 * al1 + su1;

#pragma unroll
        for (int nt = 0; nt < 8; nt++) {
            accO[nt][0] *= al0; accO[nt][1] *= al0;
            accO[nt][2] *= al1; accO[nt][3] *= al1;
        }

        // ---- O += P @ V (P packed in registers from accS) ----
#pragma unroll
        for (int kk = 0; kk < 4; kk++) {
            unsigned ph[4], pl_[4];
            split2pack(accS[2 * kk][0],     accS[2 * kk][1],     ph[0], pl_[0]);
            split2pack(accS[2 * kk][2],     accS[2 * kk][3],     ph[1], pl_[1]);
            split2pack(accS[2 * kk + 1][0], accS[2 * kk + 1][1], ph[2], pl_[2]);
            split2pack(accS[2 * kk + 1][2], accS[2 * kk + 1][3], ph[3], pl_[3]);
#pragma unroll
            for (int nt = 0; nt < 8; nt++) {
                int nb = nt * 8;
                unsigned bh[2], bl[2];
                bh[0] = sVh[(8 * kk + tg)     * VPSTR + nb + g];
                bh[1] = sVh[(8 * kk + tg + 4) * VPSTR + nb + g];
                bl[0] = sVl[(8 * kk + tg)     * VPSTR + nb + g];
                bl[1] = sVl[(8 * kk + tg + 4) * VPSTR + nb + g];
                mma_bf(accO[nt], pl_, bh);
                mma_bf(accO[nt], ph, bl);
                mma_bf(accO[nt], ph, bh);
            }
        }
    }

    int n0 = b * TT + rowg0;
    int n1 = n0 + 8;
    float* np = npart + (size_t)sp * NTOK * DM + (size_t)n0 * DM + h * HSZ;
#pragma unroll
    for (int nt = 0; nt < 8; nt++) {
        int c0 = nt * 8 + 2 * tg;
        np[c0]     = accO[nt][0];
        np[c0 + 1] = accO[nt][1];
        np[(size_t)8 * DM + c0]     = accO[nt][2];
        np[(size_t)8 * DM + c0 + 1] = accO[nt][3];
    }
    if (tg == 0) {
        smax[((size_t)sp * NTOK + n0) * NH + h] = m0;
        ssum[((size_t)sp * NTOK + n0) * NH + h] = l0;
        smax[((size_t)sp * NTOK + n1) * NH + h] = m1;
        ssum[((size_t)sp * NTOK + n1) * NH + h] = l1;
    }
}

// ---------------------------------------------------------------------------
__global__ void merge_kernel(const float* __restrict__ npart,
                             const float* __restrict__ smax,
                             const float* __restrict__ ssum,
                             float* __restrict__ out) {
    int i = blockIdx.x * blockDim.x + threadIdx.x;
    if (i >= NTOK * DM / 4) return;
    int n = i / (DM / 4);
    int c4 = i % (DM / 4);
    int h = (c4 * 4) / HSZ;

    float m0 = smax[(size_t)n * NH + h];
    float m1 = smax[((size_t)NTOK + n) * NH + h];
    float l0 = ssum[(size_t)n * NH + h];
    float l1 = ssum[((size_t)NTOK + n) * NH + h];
    float m = fmaxf(m0, m1);
    float w0 = __expf(m0 - m), w1 = __expf(m1 - m);
    float inv = 1.0f / (l0 * w0 + l1 * w1);

    float4 a = ((const float4*)npart)[i];
    float4 bq = ((const float4*)(npart + (size_t)NTOK * DM))[i];
    float4 o;
    o.x = (a.x * w0 + bq.x * w1) * inv;
    o.y = (a.y * w0 + bq.y * w1) * inv;
    o.z = (a.z * w0 + bq.z * w1) * inv;
    o.w = (a.w * w0 + bq.w * w1) * inv;
    ((float4*)out)[i] = o;
}

// ---------------------------------------------------------------------------
__global__ void zero_kernel(float* red) { red[0] = 0.f; red[1] = 0.f; }

__global__ void loss_kernel(const float* __restrict__ logits, const int* __restrict__ tgt,
                            float* __restrict__ red) {
    int r = blockIdx.x;
    int tid = threadIdx.x;
    int warp = tid >> 5, lane = tid & 31;
    const float* row = logits + (size_t)r * VOC;
    __shared__ float rbuf[8];

    float lmax = -INFINITY;
    for (int c = tid; c < VOC; c += 256) lmax = fmaxf(lmax, row[c]);
    lmax = warpMax(lmax);
    if (lane == 0) rbuf[warp] = lmax;
    __syncthreads();
    float gmax = -INFINITY;
#pragma unroll
    for (int w = 0; w < 8; w++) gmax = fmaxf(gmax, rbuf[w]);
    __syncthreads();

    float lsum = 0.f;
    for (int c = tid; c < VOC; c += 256) lsum += __expf(row[c] - gmax);
    lsum = warpSum(lsum);
    if (lane == 0) rbuf[warp] = lsum;
    __syncthreads();
    if (tid == 0) {
        float gsum = 0.f;
#pragma unroll
        for (int w = 0; w < 8; w++) gsum += rbuf[w];
        int tg = tgt[r];
        float lp = row[tg] - gmax - logf(gsum);
        float m = (tg != 0) ? 1.0f : 0.0f;
        atomicAdd(&red[0], -lp * m);
        atomicAdd(&red[1], m);
    }
}

__global__ void finalize_kernel(const float* __restrict__ red, float* __restrict__ outp) {
    outp[0] = red[0] / red[1];
}

// ---------------------------------------------------------------------------
extern "C" void kernel_launch(void* const* d_in, const int* in_sizes, int n_in,
                              void* d_out, int out_size) {
    const int*   toks = (const int*)d_in[0];
    const int*   tgts = (const int*)d_in[1];
    const float* temb = (const float*)d_in[2];
    const float* pemb = (const float*)d_in[3];
    const float* Wq   = (const float*)d_in[4];
    const float* Wk   = (const float*)d_in[5];
    const float* Wv   = (const float*)d_in[6];
    const float* Wo   = (const float*)d_in[7];
    const float* bo   = (const float*)d_in[8];
    const float* ln1g = (const float*)d_in[9];
    const float* ln1b = (const float*)d_in[10];
    const float* ln2g = (const float*)d_in[11];
    const float* ln2b = (const float*)d_in[12];
    const float* W1   = (const float*)d_in[13];
    const float* b1   = (const float*)d_in[14];
    const float* W2   = (const float*)d_in[15];
    const float* b2   = (const float*)d_in[16];
    const float* lnfg = (const float*)d_in[17];
    const float* lnfb = (const float*)d_in[18];
    const float* Wout = (const float*)d_in[19];
    const float* bout = (const float*)d_in[20];

    float *x, *h, *q, *k, *v, *a, *ff, *red, *lfb, *part, *sm_, *sl_;
    cudaGetSymbolAddress((void**)&x,    g_x);
    cudaGetSymbolAddress((void**)&h,    g_h);
    cudaGetSymbolAddress((void**)&q,    g_q);
    cudaGetSymbolAddress((void**)&k,    g_k);
    cudaGetSymbolAddress((void**)&v,    g_v);
    cudaGetSymbolAddress((void**)&a,    g_a);
    cudaGetSymbolAddress((void**)&ff,   g_ff);
    cudaGetSymbolAddress((void**)&red,  g_red);
    cudaGetSymbolAddress((void**)&lfb,  g_logits_fb);
    cudaGetSymbolAddress((void**)&part, g_part);
    cudaGetSymbolAddress((void**)&sm_,  g_sm);
    cudaGetSymbolAddress((void**)&sl_,  g_sl);

    cudaFuncSetAttribute((const void*)tgemm<1,0,0,0,1>, cudaFuncAttributeMaxDynamicSharedMemorySize, SMEM_MT1);
    cudaFuncSetAttribute((const void*)tgemm<1,1,1,0,0>, cudaFuncAttributeMaxDynamicSharedMemorySize, SMEM_MT1);
    cudaFuncSetAttribute((const void*)tgemm<2,1,0,1,0>, cudaFuncAttributeMaxDynamicSharedMemorySize, SMEM_MT2);
    cudaFuncSetAttribute((const void*)tgemm<2,1,0,0,0>, cudaFuncAttributeMaxDynamicSharedMemorySize, SMEM_MT2);
    cudaFuncSetAttribute((const void*)flash_mma,        cudaFuncAttributeMaxDynamicSharedMemorySize, FLASH_SMEM);

    embed_kernel<<<(NTOK * DM / 4 + 255) / 256, 256>>>(toks, temb, pemb, x);

    for (int l = 0; l < NL; l++) {
        ln_kernel<<<NTOK, 128>>>(x, h, ln1g + l * DM, ln1b + l * DM);

        tgemm<1,0,0,0,1><<<dim3(1, NTOK / 64, 24), 256, SMEM_MT1>>>(
            h,
            Wq + (size_t)l * NH * DM * HSZ,
            Wk + (size_t)l * NH * DM * HSZ,
            Wv + (size_t)l * NH * DM * HSZ,
            nullptr, nullptr,
            q, k, v,
            DM, DM, HSZ, DM, (long)DM * HSZ, HSZ);

        flash_mma<<<dim3(TT / 128, NH, BT * 2), 256, FLASH_SMEM>>>(q, k, v, part, sm_, sl_);
        merge_kernel<<<(NTOK * DM / 4 + 255) / 256, 256>>>(part, sm_, sl_, a);

        tgemm<1,1,1,0,0><<<dim3(DM / 64, NTOK / 64, 1), 256, SMEM_MT1>>>(
            a, Wo + (size_t)l * DM * DM, nullptr, nullptr,
            bo + l * DM, x, x, nullptr, nullptr,
            DM, DM, DM, DM, 0, 0);

        ln_kernel<<<NTOK, 128>>>(x, h, ln2g + l * DM, ln2b + l * DM);

        // FF1 + bias + relu (R14 config: BM=128, BN=64)
        tgemm<2,1,0,1,0><<<dim3(FFD / 64, NTOK / 128, 1), 256, SMEM_MT2>>>(
            h, W1 + (size_t)l * DM * FFD, nullptr, nullptr,
            b1 + (size_t)l * FFD, nullptr, ff, nullptr, nullptr,
            DM, DM, FFD, FFD, 0, 0);
        // FF2 + bias + residual
        tgemm<1,1,1,0,0><<<dim3(DM / 64, NTOK / 64, 1), 256, SMEM_MT1>>>(
            ff, W2 + (size_t)l * FFD * DM, nullptr, nullptr,
            b2 + l * DM, x, x, nullptr, nullptr,
            FFD, FFD, DM, DM, 0, 0);
    }

    ln_kernel<<<NTOK, 128>>>(x, h, lnfg, lnfb);

    const long logitsElems = (long)NTOK * VOC;
    float* logits = ((long)out_size >= logitsElems) ? (float*)d_out : lfb;

    // logits GEMM (R14 config: BM=128, BN=64)
    tgemm<2,1,0,0,0><<<dim3(VOC / 64, NTOK / 128, 1), 256, SMEM_MT2>>>(
        h, Wout, nullptr, nullptr,
        bout, nullptr, logits, nullptr, nullptr,
        DM, DM, VOC, VOC, 0, 0);

    if ((long)out_size != logitsElems) {
        zero_kernel<<<1, 1>>>(red);
        loss_kernel<<<NTOK, 256>>>(logits, tgts, red);
        float* lossOut;
        if ((long)out_size > logitsElems)
            lossOut = (float*)d_out + logitsElems;
        else
            lossOut = (float*)d_out + (out_size - 1);
        finalize_kernel<<<1, 1>>>(red, lossOut);
    }
}